// round 1
// baseline (speedup 1.0000x reference)
#include <cuda_runtime.h>
#include <cuda_bf16.h>

#define IMG_H 256
#define IMG_W 256
#define TILE_W 128
#define TILE_H 32
#define SW 132   // padded smem row width (need 131)

__global__ __launch_bounds__(256, 6)
void Blur2_kernel(const float* __restrict__ in,
                  const float* __restrict__ kern,
                  float* __restrict__ out) {
    __shared__ float s_in[TILE_H + 3][SW];
    __shared__ float s_h[TILE_H + 3][TILE_W];

    const int tx = threadIdx.x;   // 0..31
    const int ty = threadIdx.y;   // 0..7
    const int ox0 = blockIdx.x * TILE_W;
    const int oy0 = blockIdx.y * TILE_H;
    const int z   = blockIdx.z;   // n*c fold
    const float* __restrict__ inp = in + (size_t)z * (IMG_H * IMG_W);

    // ---- load input tile with halo: rows oy0-2 .. oy0+TILE_H, cols ox0-2 .. ox0+TILE_W ----
    #pragma unroll
    for (int i = 0; i < 5; i++) {
        const int r = ty + 8 * i;
        if (r < TILE_H + 3) {
            const int gy = oy0 - 2 + r;
            const bool rok = ((unsigned)gy < IMG_H);
            const float* rowp = inp + (size_t)gy * IMG_W;
            #pragma unroll
            for (int j = 0; j < 5; j++) {
                const int c = tx + 32 * j;
                if (c < TILE_W + 3) {
                    const int gx = ox0 - 2 + c;
                    float v = 0.0f;
                    if (rok && (unsigned)gx < IMG_W) v = rowp[gx];
                    s_in[r][c] = v;
                }
            }
        }
    }

    // ---- derive separable factors from the 2D kernel (rank-1 outer product) ----
    // out[y,x] = sum_{a,b} k[a][b] * in[y+1-a, x+1-b],  k[a][b] = u[a]*w[b]
    const float k00 = kern[0];
    const float rk  = 1.0f / k00;
    const float w0 = kern[0], w1 = kern[1], w2 = kern[2], w3 = kern[3];
    const float u0 = 1.0f;
    const float u1 = kern[4]  * rk;
    const float u2 = kern[8]  * rk;
    const float u3 = kern[12] * rk;

    __syncthreads();

    // ---- horizontal pass: h[r][c] = sum_d w[3-d] * s_in[r][c+d] ----
    #pragma unroll
    for (int i = 0; i < 5; i++) {
        const int r = ty + 8 * i;
        if (r < TILE_H + 3) {
            #pragma unroll
            for (int j = 0; j < 4; j++) {
                const int c = tx + 32 * j;
                const float v = w3 * s_in[r][c]
                              + w2 * s_in[r][c + 1]
                              + w1 * s_in[r][c + 2]
                              + w0 * s_in[r][c + 3];
                s_h[r][c] = v;
            }
        }
    }
    __syncthreads();

    // ---- vertical pass + float4 store: out[ly][c] = sum_d u[3-d] * h[ly+d][c] ----
    const int c0 = tx * 4;
    #pragma unroll
    for (int rr = 0; rr < 4; rr++) {
        const int ly = ty + 8 * rr;
        const float4 a0 = *(const float4*)&s_h[ly + 0][c0];
        const float4 a1 = *(const float4*)&s_h[ly + 1][c0];
        const float4 a2 = *(const float4*)&s_h[ly + 2][c0];
        const float4 a3 = *(const float4*)&s_h[ly + 3][c0];
        float4 o;
        o.x = u3 * a0.x + u2 * a1.x + u1 * a2.x + u0 * a3.x;
        o.y = u3 * a0.y + u2 * a1.y + u1 * a2.y + u0 * a3.y;
        o.z = u3 * a0.z + u2 * a1.z + u1 * a2.z + u0 * a3.z;
        o.w = u3 * a0.w + u2 * a1.w + u1 * a2.w + u0 * a3.w;
        const int gy = oy0 + ly;
        *(float4*)&out[((size_t)z * IMG_H + gy) * IMG_W + ox0 + c0] = o;
    }
}

extern "C" void kernel_launch(void* const* d_in, const int* in_sizes, int n_in,
                              void* d_out, int out_size) {
    // metadata order: input [8,128,256,256] f32, kernel [4,4] f32
    int xi = 0, ki = 1;
    if (n_in >= 2 && in_sizes[0] == 16) { xi = 1; ki = 0; }  // robustness to ordering
    const float* x  = (const float*)d_in[xi];
    const float* k  = (const float*)d_in[ki];
    float* o        = (float*)d_out;

    const int nc = in_sizes[xi] / (IMG_H * IMG_W);  // 8*128 = 1024
    dim3 grid(IMG_W / TILE_W, IMG_H / TILE_H, nc);  // (2, 8, 1024)
    dim3 block(32, 8);
    Blur2_kernel<<<grid, block>>>(x, k, o);
}

// round 2
// speedup vs baseline: 2.3999x; 2.3999x over previous
#include <cuda_runtime.h>
#include <cuda_bf16.h>

#define IMG_H 256
#define IMG_W 256
#define ROWS_PER_THREAD 16

// Register-rolling separable 4x4 depthwise blur.
// out[y,x] = sum_{a,b} k[a][b] * in[y+1-a, x+1-b]   (zero pad outside)
// k is rank-1: k[a][b] = u[a]*w[b], w[b]=k[0][b], u[a]=k[a][0]/k[0][0].
//
// Thread layout: 256 threads/CTA. lane = t&63 covers 4 output cols (x0=4*lane),
// strip = t>>6 selects one of 4 row-strips of 16 rows. CTA covers 64 rows x 256 cols.
__global__ __launch_bounds__(256)
void Blur2_kernel(const float* __restrict__ in,
                  const float* __restrict__ kern,
                  float* __restrict__ out) {
    const int t     = threadIdx.x;
    const int lane  = t & 63;          // column group: 0..63
    const int strip = t >> 6;          // 0..3
    const int x0    = lane << 2;       // 0..252
    const int z     = blockIdx.y;      // n*c fold (1024)
    const int y0    = blockIdx.x * 64 + strip * ROWS_PER_THREAD;

    const float* __restrict__ base  = in  + (size_t)z * (IMG_H * IMG_W);
    float*       __restrict__ obase = out + (size_t)z * (IMG_H * IMG_W);

    // separable factors (rank-1 kernel)
    const float w0 = kern[0], w1 = kern[1], w2 = kern[2], w3 = kern[3];
    const float rk = 1.0f / w0;
    const float u1 = kern[4] * rk, u2 = kern[8] * rk, u3 = kern[12] * rk;

    const bool has_l = (lane > 0);
    const bool has_r = (lane < 63);

    // horizontal 4-tap over one input row -> float4 of h-values for cols x0..x0+3
    auto hrow = [&](int gy) -> float4 {
        float4 h = make_float4(0.f, 0.f, 0.f, 0.f);
        if ((unsigned)gy < (unsigned)IMG_H) {
            const float* rp = base + gy * IMG_W + x0;
            const float4 m = *(const float4*)rp;                 // cols x0..x0+3 (16B aligned)
            float cm2 = 0.f, cm1 = 0.f, cp4 = 0.f;
            if (has_l) { const float2 l = *(const float2*)(rp - 2); cm2 = l.x; cm1 = l.y; }
            if (has_r) { cp4 = rp[4]; }
            h.x = fmaf(w3, cm2, fmaf(w2, cm1, fmaf(w1, m.x, w0 * m.y)));
            h.y = fmaf(w3, cm1, fmaf(w2, m.x, fmaf(w1, m.y, w0 * m.z)));
            h.z = fmaf(w3, m.x, fmaf(w2, m.y, fmaf(w1, m.z, w0 * m.w)));
            h.w = fmaf(w3, m.y, fmaf(w2, m.z, fmaf(w1, m.w, w0 * cp4)));
        }
        return h;
    };

    // vertical rolling ring: h0=row y-2, h1=y-1, h2=y, h3=y+1
    float4 h0 = hrow(y0 - 2);
    float4 h1 = hrow(y0 - 1);
    float4 h2 = hrow(y0);

    #pragma unroll
    for (int i = 0; i < ROWS_PER_THREAD; i++) {
        const float4 h3 = hrow(y0 + 1 + i);
        float4 o;
        o.x = fmaf(u3, h0.x, fmaf(u2, h1.x, fmaf(u1, h2.x, h3.x)));
        o.y = fmaf(u3, h0.y, fmaf(u2, h1.y, fmaf(u1, h2.y, h3.y)));
        o.z = fmaf(u3, h0.z, fmaf(u2, h1.z, fmaf(u1, h2.z, h3.z)));
        o.w = fmaf(u3, h0.w, fmaf(u2, h1.w, fmaf(u1, h2.w, h3.w)));
        *(float4*)(obase + (y0 + i) * IMG_W + x0) = o;
        h0 = h1; h1 = h2; h2 = h3;
    }
}

extern "C" void kernel_launch(void* const* d_in, const int* in_sizes, int n_in,
                              void* d_out, int out_size) {
    int xi = 0, ki = 1;
    if (n_in >= 2 && in_sizes[0] == 16) { xi = 1; ki = 0; }
    const float* x = (const float*)d_in[xi];
    const float* k = (const float*)d_in[ki];
    float* o       = (float*)d_out;

    const int nc = in_sizes[xi] / (IMG_H * IMG_W);   // 1024
    dim3 grid(IMG_H / 64, nc);                        // (4, 1024)
    dim3 block(256);
    Blur2_kernel<<<grid, block>>>(x, k, o);
}

// round 3
// speedup vs baseline: 2.7693x; 1.1539x over previous
#include <cuda_runtime.h>
#include <cuda_bf16.h>

#define IMG_H 256
#define IMG_W 256
#define ROWS_PER_THREAD 16

struct RowIn { float4 m; float2 l; float r; };

// Register-rolling separable 4x4 depthwise blur, 4-row load batching for MLP.
// out[y,x] = sum_{a,b} k[a][b] * in[y+1-a, x+1-b]   (zero pad outside)
// k is rank-1: k[a][b] = u[a]*w[b], w[b]=k[0][b], u[a]=k[a][0]/k[0][0].
__global__ __launch_bounds__(256)
void Blur2_kernel(const float* __restrict__ in,
                  const float* __restrict__ kern,
                  float* __restrict__ out) {
    const int t     = threadIdx.x;
    const int lane  = t & 63;          // column group: 0..63
    const int strip = t >> 6;          // 0..3
    const int x0    = lane << 2;       // 0..252
    const int z     = blockIdx.y;      // n*c fold (1024)
    const int y0    = blockIdx.x * 64 + strip * ROWS_PER_THREAD;

    const float* __restrict__ base  = in  + (size_t)z * (IMG_H * IMG_W);
    float*       __restrict__ obase = out + (size_t)z * (IMG_H * IMG_W);

    // separable factors (rank-1 kernel)
    const float w0 = kern[0], w1 = kern[1], w2 = kern[2], w3 = kern[3];
    const float rk = 1.0f / w0;
    const float u1 = kern[4] * rk, u2 = kern[8] * rk, u3 = kern[12] * rk;

    const bool has_l = (lane > 0);
    const bool has_r = (lane < 63);

    auto loadrow = [&](int gy) -> RowIn {
        RowIn v;
        v.m = make_float4(0.f, 0.f, 0.f, 0.f);
        v.l = make_float2(0.f, 0.f);
        v.r = 0.f;
        if ((unsigned)gy < (unsigned)IMG_H) {
            const float* rp = base + gy * IMG_W + x0;
            v.m = *(const float4*)rp;
            if (has_l) v.l = *(const float2*)(rp - 2);
            if (has_r) v.r = rp[4];
        }
        return v;
    };

    auto hcalc = [&](const RowIn& v) -> float4 {
        float4 h;
        h.x = fmaf(w3, v.l.x, fmaf(w2, v.l.y, fmaf(w1, v.m.x, w0 * v.m.y)));
        h.y = fmaf(w3, v.l.y, fmaf(w2, v.m.x, fmaf(w1, v.m.y, w0 * v.m.z)));
        h.z = fmaf(w3, v.m.x, fmaf(w2, v.m.y, fmaf(w1, v.m.z, w0 * v.m.w)));
        h.w = fmaf(w3, v.m.y, fmaf(w2, v.m.z, fmaf(w1, v.m.w, w0 * v.r)));
        return h;
    };

    // prologue: rows y0-2, y0-1, y0 (batched loads)
    RowIn p0 = loadrow(y0 - 2);
    RowIn p1 = loadrow(y0 - 1);
    RowIn p2 = loadrow(y0);
    float4 h0 = hcalc(p0);
    float4 h1 = hcalc(p1);
    float4 h2 = hcalc(p2);

    #pragma unroll
    for (int i = 0; i < ROWS_PER_THREAD; i += 4) {
        // batch 12 independent LDGs for the next 4 rows
        RowIn a = loadrow(y0 + 1 + i);
        RowIn b = loadrow(y0 + 2 + i);
        RowIn c = loadrow(y0 + 3 + i);
        RowIn d = loadrow(y0 + 4 + i);

        float* op = obase + (y0 + i) * IMG_W + x0;

        float4 h3 = hcalc(a);
        float4 o;
        o.x = fmaf(u3, h0.x, fmaf(u2, h1.x, fmaf(u1, h2.x, h3.x)));
        o.y = fmaf(u3, h0.y, fmaf(u2, h1.y, fmaf(u1, h2.y, h3.y)));
        o.z = fmaf(u3, h0.z, fmaf(u2, h1.z, fmaf(u1, h2.z, h3.z)));
        o.w = fmaf(u3, h0.w, fmaf(u2, h1.w, fmaf(u1, h2.w, h3.w)));
        *(float4*)op = o;

        float4 h4 = hcalc(b);
        o.x = fmaf(u3, h1.x, fmaf(u2, h2.x, fmaf(u1, h3.x, h4.x)));
        o.y = fmaf(u3, h1.y, fmaf(u2, h2.y, fmaf(u1, h3.y, h4.y)));
        o.z = fmaf(u3, h1.z, fmaf(u2, h2.z, fmaf(u1, h3.z, h4.z)));
        o.w = fmaf(u3, h1.w, fmaf(u2, h2.w, fmaf(u1, h3.w, h4.w)));
        *(float4*)(op + IMG_W) = o;

        float4 h5 = hcalc(c);
        o.x = fmaf(u3, h2.x, fmaf(u2, h3.x, fmaf(u1, h4.x, h5.x)));
        o.y = fmaf(u3, h2.y, fmaf(u2, h3.y, fmaf(u1, h4.y, h5.y)));
        o.z = fmaf(u3, h2.z, fmaf(u2, h3.z, fmaf(u1, h4.z, h5.z)));
        o.w = fmaf(u3, h2.w, fmaf(u2, h3.w, fmaf(u1, h4.w, h5.w)));
        *(float4*)(op + 2 * IMG_W) = o;

        float4 h6 = hcalc(d);
        o.x = fmaf(u3, h3.x, fmaf(u2, h4.x, fmaf(u1, h5.x, h6.x)));
        o.y = fmaf(u3, h3.y, fmaf(u2, h4.y, fmaf(u1, h5.y, h6.y)));
        o.z = fmaf(u3, h3.z, fmaf(u2, h4.z, fmaf(u1, h5.z, h6.z)));
        o.w = fmaf(u3, h3.w, fmaf(u2, h4.w, fmaf(u1, h5.w, h6.w)));
        *(float4*)(op + 3 * IMG_W) = o;

        h0 = h4; h1 = h5; h2 = h6;
    }
}

extern "C" void kernel_launch(void* const* d_in, const int* in_sizes, int n_in,
                              void* d_out, int out_size) {
    int xi = 0, ki = 1;
    if (n_in >= 2 && in_sizes[0] == 16) { xi = 1; ki = 0; }
    const float* x = (const float*)d_in[xi];
    const float* k = (const float*)d_in[ki];
    float* o       = (float*)d_out;

    const int nc = in_sizes[xi] / (IMG_H * IMG_W);   // 1024
    dim3 grid(IMG_H / 64, nc);                        // (4, 1024)
    dim3 block(256);
    Blur2_kernel<<<grid, block>>>(x, k, o);
}

// round 4
// speedup vs baseline: 2.8059x; 1.0132x over previous
#include <cuda_runtime.h>
#include <cuda_bf16.h>

#define IMG_H 256
#define IMG_W 256
#define ROWS_PER_THREAD 16
#define FULLMASK 0xffffffffu

struct Row { float4 m; float lx, ly, r; };

// Register-rolling separable 4x4 depthwise blur.
// Warp-shuffle halo: each warp owns a 128-col segment; per row each thread
// does one float4 LDG; halo values come from neighbor lanes via shfl.
// out[y,x] = sum_{a,b} k[a][b] * in[y+1-a, x+1-b]   (zero pad outside)
__global__ __launch_bounds__(256)
void Blur2_kernel(const float* __restrict__ in,
                  const float* __restrict__ kern,
                  float* __restrict__ out) {
    const int t     = threadIdx.x;
    const int lane  = t & 31;
    const int warp  = t >> 5;           // 0..7
    const int seg   = warp & 1;         // column segment: 0 or 1
    const int strip = warp >> 1;        // 0..3
    const int xg    = seg * 128 + lane * 4;   // global col of first output
    const int z     = blockIdx.y;       // n*c fold (1024)
    const int y0    = blockIdx.x * 64 + strip * ROWS_PER_THREAD;

    const float* __restrict__ base  = in  + (size_t)z * (IMG_H * IMG_W);
    float*       __restrict__ obase = out + (size_t)z * (IMG_H * IMG_W);

    // separable factors (rank-1 kernel)
    const float w0 = kern[0], w1 = kern[1], w2 = kern[2], w3 = kern[3];
    const float rk = 1.0f / w0;
    const float u1 = kern[4] * rk, u2 = kern[8] * rk, u3 = kern[12] * rk;

    const bool left_edge_load  = (lane == 0)  && (seg == 1);  // need cols xg-2, xg-1
    const bool right_edge_load = (lane == 31) && (seg == 0);  // need col xg+4

    auto loadrow = [&](int gy) -> Row {
        Row v;
        v.m = make_float4(0.f, 0.f, 0.f, 0.f);
        v.lx = 0.f; v.ly = 0.f; v.r = 0.f;
        if ((unsigned)gy < (unsigned)IMG_H) {
            const float* rp = base + gy * IMG_W + xg;
            v.m = *(const float4*)rp;
            if (left_edge_load)  { const float2 e = *(const float2*)(rp - 2); v.lx = e.x; v.ly = e.y; }
            if (right_edge_load) { v.r = rp[4]; }
        }
        return v;
    };

    auto hcalc = [&](const Row& v) -> float4 {
        float cm2 = __shfl_up_sync(FULLMASK, v.m.z, 1);
        float cm1 = __shfl_up_sync(FULLMASK, v.m.w, 1);
        float p4  = __shfl_down_sync(FULLMASK, v.m.x, 1);
        if (lane == 0)  { cm2 = v.lx; cm1 = v.ly; }
        if (lane == 31) { p4 = v.r; }
        float4 h;
        h.x = fmaf(w3, cm2,   fmaf(w2, cm1,   fmaf(w1, v.m.x, w0 * v.m.y)));
        h.y = fmaf(w3, cm1,   fmaf(w2, v.m.x, fmaf(w1, v.m.y, w0 * v.m.z)));
        h.z = fmaf(w3, v.m.x, fmaf(w2, v.m.y, fmaf(w1, v.m.z, w0 * v.m.w)));
        h.w = fmaf(w3, v.m.y, fmaf(w2, v.m.z, fmaf(w1, v.m.w, w0 * p4)));
        return h;
    };

    // prologue: rows y0-2, y0-1, y0
    Row p0 = loadrow(y0 - 2);
    Row p1 = loadrow(y0 - 1);
    Row p2 = loadrow(y0);
    float4 h0 = hcalc(p0);
    float4 h1 = hcalc(p1);
    float4 h2 = hcalc(p2);

    #pragma unroll
    for (int i = 0; i < ROWS_PER_THREAD; i += 4) {
        // batch independent LDGs for the next 4 rows
        Row a = loadrow(y0 + 1 + i);
        Row b = loadrow(y0 + 2 + i);
        Row c = loadrow(y0 + 3 + i);
        Row d = loadrow(y0 + 4 + i);

        float* op = obase + (y0 + i) * IMG_W + xg;

        float4 h3 = hcalc(a);
        float4 o;
        o.x = fmaf(u3, h0.x, fmaf(u2, h1.x, fmaf(u1, h2.x, h3.x)));
        o.y = fmaf(u3, h0.y, fmaf(u2, h1.y, fmaf(u1, h2.y, h3.y)));
        o.z = fmaf(u3, h0.z, fmaf(u2, h1.z, fmaf(u1, h2.z, h3.z)));
        o.w = fmaf(u3, h0.w, fmaf(u2, h1.w, fmaf(u1, h2.w, h3.w)));
        *(float4*)op = o;

        float4 h4 = hcalc(b);
        o.x = fmaf(u3, h1.x, fmaf(u2, h2.x, fmaf(u1, h3.x, h4.x)));
        o.y = fmaf(u3, h1.y, fmaf(u2, h2.y, fmaf(u1, h3.y, h4.y)));
        o.z = fmaf(u3, h1.z, fmaf(u2, h2.z, fmaf(u1, h3.z, h4.z)));
        o.w = fmaf(u3, h1.w, fmaf(u2, h2.w, fmaf(u1, h3.w, h4.w)));
        *(float4*)(op + IMG_W) = o;

        float4 h5 = hcalc(c);
        o.x = fmaf(u3, h2.x, fmaf(u2, h3.x, fmaf(u1, h4.x, h5.x)));
        o.y = fmaf(u3, h2.y, fmaf(u2, h3.y, fmaf(u1, h4.y, h5.y)));
        o.z = fmaf(u3, h2.z, fmaf(u2, h3.z, fmaf(u1, h4.z, h5.z)));
        o.w = fmaf(u3, h2.w, fmaf(u2, h3.w, fmaf(u1, h4.w, h5.w)));
        *(float4*)(op + 2 * IMG_W) = o;

        float4 h6 = hcalc(d);
        o.x = fmaf(u3, h3.x, fmaf(u2, h4.x, fmaf(u1, h5.x, h6.x)));
        o.y = fmaf(u3, h3.y, fmaf(u2, h4.y, fmaf(u1, h5.y, h6.y)));
        o.z = fmaf(u3, h3.z, fmaf(u2, h4.z, fmaf(u1, h5.z, h6.z)));
        o.w = fmaf(u3, h3.w, fmaf(u2, h4.w, fmaf(u1, h5.w, h6.w)));
        *(float4*)(op + 3 * IMG_W) = o;

        h0 = h4; h1 = h5; h2 = h6;
    }
}

extern "C" void kernel_launch(void* const* d_in, const int* in_sizes, int n_in,
                              void* d_out, int out_size) {
    int xi = 0, ki = 1;
    if (n_in >= 2 && in_sizes[0] == 16) { xi = 1; ki = 0; }
    const float* x = (const float*)d_in[xi];
    const float* k = (const float*)d_in[ki];
    float* o       = (float*)d_out;

    const int nc = in_sizes[xi] / (IMG_H * IMG_W);   // 1024
    dim3 grid(IMG_H / 64, nc);                        // (4, 1024)
    dim3 block(256);
    Blur2_kernel<<<grid, block>>>(x, k, o);
}

// round 5
// speedup vs baseline: 2.8272x; 1.0076x over previous
#include <cuda_runtime.h>
#include <cuda_bf16.h>

#define IMG_H 256
#define IMG_W 256
#define ROWS_PER_THREAD 16
#define FULLMASK 0xffffffffu

struct Row { float4 m; float lx, ly, r; };

__device__ __forceinline__ void stcs4(float* p, float4 v) {
    asm volatile("st.global.cs.v4.f32 [%0], {%1,%2,%3,%4};"
                 :: "l"(p), "f"(v.x), "f"(v.y), "f"(v.z), "f"(v.w) : "memory");
}

// Register-rolling separable 4x4 depthwise blur.
// Warp-shuffle halo + streaming (evict-first) output stores.
// out[y,x] = sum_{a,b} k[a][b] * in[y+1-a, x+1-b]   (zero pad outside)
__global__ __launch_bounds__(256)
void Blur2_kernel(const float* __restrict__ in,
                  const float* __restrict__ kern,
                  float* __restrict__ out) {
    const int t     = threadIdx.x;
    const int lane  = t & 31;
    const int warp  = t >> 5;           // 0..7
    const int seg   = warp & 1;         // column segment: 0 or 1
    const int strip = warp >> 1;        // 0..3
    const int xg    = seg * 128 + lane * 4;   // global col of first output
    const int z     = blockIdx.y;       // n*c fold (1024)
    const int y0    = blockIdx.x * 64 + strip * ROWS_PER_THREAD;

    const float* __restrict__ base  = in  + (size_t)z * (IMG_H * IMG_W);
    float*       __restrict__ obase = out + (size_t)z * (IMG_H * IMG_W);

    // separable factors (rank-1 kernel)
    const float w0 = kern[0], w1 = kern[1], w2 = kern[2], w3 = kern[3];
    const float rk = 1.0f / w0;
    const float u1 = kern[4] * rk, u2 = kern[8] * rk, u3 = kern[12] * rk;

    const bool left_edge_load  = (lane == 0)  && (seg == 1);  // need cols xg-2, xg-1
    const bool right_edge_load = (lane == 31) && (seg == 0);  // need col xg+4

    auto loadrow = [&](int gy) -> Row {
        Row v;
        v.m = make_float4(0.f, 0.f, 0.f, 0.f);
        v.lx = 0.f; v.ly = 0.f; v.r = 0.f;
        if ((unsigned)gy < (unsigned)IMG_H) {
            const float* rp = base + gy * IMG_W + xg;
            v.m = *(const float4*)rp;
            if (left_edge_load)  { const float2 e = *(const float2*)(rp - 2); v.lx = e.x; v.ly = e.y; }
            if (right_edge_load) { v.r = rp[4]; }
        }
        return v;
    };

    auto hcalc = [&](const Row& v) -> float4 {
        float cm2 = __shfl_up_sync(FULLMASK, v.m.z, 1);
        float cm1 = __shfl_up_sync(FULLMASK, v.m.w, 1);
        float p4  = __shfl_down_sync(FULLMASK, v.m.x, 1);
        if (lane == 0)  { cm2 = v.lx; cm1 = v.ly; }
        if (lane == 31) { p4 = v.r; }
        float4 h;
        h.x = fmaf(w3, cm2,   fmaf(w2, cm1,   fmaf(w1, v.m.x, w0 * v.m.y)));
        h.y = fmaf(w3, cm1,   fmaf(w2, v.m.x, fmaf(w1, v.m.y, w0 * v.m.z)));
        h.z = fmaf(w3, v.m.x, fmaf(w2, v.m.y, fmaf(w1, v.m.z, w0 * v.m.w)));
        h.w = fmaf(w3, v.m.y, fmaf(w2, v.m.z, fmaf(w1, v.m.w, w0 * p4)));
        return h;
    };

    // prologue: rows y0-2, y0-1, y0
    Row p0 = loadrow(y0 - 2);
    Row p1 = loadrow(y0 - 1);
    Row p2 = loadrow(y0);
    float4 h0 = hcalc(p0);
    float4 h1 = hcalc(p1);
    float4 h2 = hcalc(p2);

    #pragma unroll
    for (int i = 0; i < ROWS_PER_THREAD; i += 4) {
        // batch independent LDGs for the next 4 rows
        Row a = loadrow(y0 + 1 + i);
        Row b = loadrow(y0 + 2 + i);
        Row c = loadrow(y0 + 3 + i);
        Row d = loadrow(y0 + 4 + i);

        float* op = obase + (y0 + i) * IMG_W + xg;

        float4 h3 = hcalc(a);
        float4 o;
        o.x = fmaf(u3, h0.x, fmaf(u2, h1.x, fmaf(u1, h2.x, h3.x)));
        o.y = fmaf(u3, h0.y, fmaf(u2, h1.y, fmaf(u1, h2.y, h3.y)));
        o.z = fmaf(u3, h0.z, fmaf(u2, h1.z, fmaf(u1, h2.z, h3.z)));
        o.w = fmaf(u3, h0.w, fmaf(u2, h1.w, fmaf(u1, h2.w, h3.w)));
        stcs4(op, o);

        float4 h4 = hcalc(b);
        o.x = fmaf(u3, h1.x, fmaf(u2, h2.x, fmaf(u1, h3.x, h4.x)));
        o.y = fmaf(u3, h1.y, fmaf(u2, h2.y, fmaf(u1, h3.y, h4.y)));
        o.z = fmaf(u3, h1.z, fmaf(u2, h2.z, fmaf(u1, h3.z, h4.z)));
        o.w = fmaf(u3, h1.w, fmaf(u2, h2.w, fmaf(u1, h3.w, h4.w)));
        stcs4(op + IMG_W, o);

        float4 h5 = hcalc(c);
        o.x = fmaf(u3, h2.x, fmaf(u2, h3.x, fmaf(u1, h4.x, h5.x)));
        o.y = fmaf(u3, h2.y, fmaf(u2, h3.y, fmaf(u1, h4.y, h5.y)));
        o.z = fmaf(u3, h2.z, fmaf(u2, h3.z, fmaf(u1, h4.z, h5.z)));
        o.w = fmaf(u3, h2.w, fmaf(u2, h3.w, fmaf(u1, h4.w, h5.w)));
        stcs4(op + 2 * IMG_W, o);

        float4 h6 = hcalc(d);
        o.x = fmaf(u3, h3.x, fmaf(u2, h4.x, fmaf(u1, h5.x, h6.x)));
        o.y = fmaf(u3, h3.y, fmaf(u2, h4.y, fmaf(u1, h5.y, h6.y)));
        o.z = fmaf(u3, h3.z, fmaf(u2, h4.z, fmaf(u1, h5.z, h6.z)));
        o.w = fmaf(u3, h3.w, fmaf(u2, h4.w, fmaf(u1, h5.w, h6.w)));
        stcs4(op + 3 * IMG_W, o);

        h0 = h4; h1 = h5; h2 = h6;
    }
}

extern "C" void kernel_launch(void* const* d_in, const int* in_sizes, int n_in,
                              void* d_out, int out_size) {
    int xi = 0, ki = 1;
    if (n_in >= 2 && in_sizes[0] == 16) { xi = 1; ki = 0; }
    const float* x = (const float*)d_in[xi];
    const float* k = (const float*)d_in[ki];
    float* o       = (float*)d_out;

    const int nc = in_sizes[xi] / (IMG_H * IMG_W);   // 1024
    dim3 grid(IMG_H / 64, nc);                        // (4, 1024)
    dim3 block(256);
    Blur2_kernel<<<grid, block>>>(x, k, o);
}